// round 2
// baseline (speedup 1.0000x reference)
#include <cuda_runtime.h>
#include <cstdint>

// Problem constants
#define TOKENS 2048
#define HIDDEN 2048
#define INTER  5632
#define NEXP   8
#define TOPK   2
#define NPAIR  (TOKENS * TOPK)   // 4096

// GEMM tiling
#define BM 64
#define BN 128
#define BK 32
#define AS_STRIDE 36    // 64x32 A tile, padded: bank = (4g+tg)%32 all-distinct
#define WS_STRIDE 136   // 32x128 W tile, padded: bank = (8tg+g)%32 all-distinct

// -------- persistent device scratch (static: no runtime allocation) --------
__device__ int   d_cnt[NEXP];
__device__ int   d_off[NEXP];
__device__ int   d_tok[NPAIR];
__device__ float d_wgt[NPAIR];
__device__ float d_hbuf[(size_t)NPAIR * INTER];   // 92.3 MB intermediate h = silu(gate)*up

// ---------------------------------------------------------------------------
// helpers
// ---------------------------------------------------------------------------
__device__ __forceinline__ uint32_t f2tf32(float f) {
    uint32_t u;
    asm("cvt.rna.tf32.f32 %0, %1;" : "=r"(u) : "f"(f));
    return u;
}

__device__ __forceinline__ void mma_tf32(float c[4], const uint32_t a[4],
                                         uint32_t b0, uint32_t b1) {
    asm volatile(
        "mma.sync.aligned.m16n8k8.row.col.f32.tf32.tf32.f32 "
        "{%0,%1,%2,%3}, {%4,%5,%6,%7}, {%8,%9}, {%0,%1,%2,%3};\n"
        : "+f"(c[0]), "+f"(c[1]), "+f"(c[2]), "+f"(c[3])
        : "r"(a[0]), "r"(a[1]), "r"(a[2]), "r"(a[3]), "r"(b0), "r"(b1));
}

// ---------------------------------------------------------------------------
// Routing: bucket 4096 (token, k) pairs by expert into compact lists.
// Single block; fully recomputes all state every call (graph-replay safe).
// ---------------------------------------------------------------------------
__global__ void route_kernel(const int* __restrict__ eidx,
                             const float* __restrict__ ew) {
    __shared__ int s_cnt[NEXP];
    __shared__ int s_off[NEXP];
    __shared__ int s_cur[NEXP];
    int t = threadIdx.x;
    if (t < NEXP) s_cnt[t] = 0;
    __syncthreads();
    for (int p = t; p < NPAIR; p += blockDim.x)
        atomicAdd(&s_cnt[eidx[p]], 1);
    __syncthreads();
    if (t == 0) {
        int o = 0;
        for (int e = 0; e < NEXP; e++) { s_off[e] = o; s_cur[e] = o; o += s_cnt[e]; }
    }
    __syncthreads();
    for (int p = t; p < NPAIR; p += blockDim.x) {
        int e = eidx[p];
        int pos = atomicAdd(&s_cur[e], 1);
        d_tok[pos] = p >> 1;          // token id (p = token*TOPK + k)
        d_wgt[pos] = ew[p];
    }
    if (t < NEXP) { d_cnt[t] = s_cnt[t]; d_off[t] = s_off[t]; }
}

// ---------------------------------------------------------------------------
// GEMM1: for each expert e, rows = gathered tokens:
//   gate = Xg @ W1[e], up = Xg @ W3[e], h = silu(gate)*up  -> d_hbuf
// Block tile: BM=64 x BN=128, 4 warps (2x2), warp tile 32x64.
// Gate and up share A fragments (W1 and W3 tiles both resident in smem).
// Grid: (m_tile FASTEST for L2 W-slab reuse, n_tile, expert)
// ---------------------------------------------------------------------------
__global__ __launch_bounds__(128)
void gemm1_kernel(const float* __restrict__ x,
                  const float* __restrict__ w1,
                  const float* __restrict__ w3) {
    const int e   = blockIdx.z;
    const int cnt = d_cnt[e];
    const int m0  = blockIdx.x * BM;
    if (m0 >= cnt) return;
    const int n0  = blockIdx.y * BN;
    const int off = d_off[e];

    __shared__ uint32_t As [BM * AS_STRIDE];
    __shared__ uint32_t W1s[BK * WS_STRIDE];
    __shared__ uint32_t W3s[BK * WS_STRIDE];

    const int tid  = threadIdx.x;
    const int lane = tid & 31, warp = tid >> 5;
    const int wm = warp >> 1, wn = warp & 1;
    const int g = lane >> 2, tg = lane & 3;

    // Per-thread A-load row pointers (4 float4 loads per tile)
    const float* aptr[4];
#pragma unroll
    for (int i = 0; i < 4; i++) {
        int f = tid + i * 128;
        int row = f >> 3;
        int gr = m0 + row;
        aptr[i] = (gr < cnt) ? (x + (size_t)d_tok[off + gr] * HIDDEN) : nullptr;
    }
    const float* w1p = w1 + (size_t)e * HIDDEN * INTER + n0;
    const float* w3p = w3 + (size_t)e * HIDDEN * INTER + n0;

    float gacc[2][8][4];
    float uacc[2][8][4];
#pragma unroll
    for (int mi = 0; mi < 2; mi++)
#pragma unroll
        for (int ni = 0; ni < 8; ni++)
#pragma unroll
            for (int r = 0; r < 4; r++) { gacc[mi][ni][r] = 0.f; uacc[mi][ni][r] = 0.f; }

    for (int k0 = 0; k0 < HIDDEN; k0 += BK) {
        // ---- A tile: 64x32 fp32 -> tf32 ----
#pragma unroll
        for (int i = 0; i < 4; i++) {
            int f = tid + i * 128;
            int row = f >> 3, col = (f & 7) * 4;
            float4 v = make_float4(0.f, 0.f, 0.f, 0.f);
            if (aptr[i]) v = *(const float4*)(aptr[i] + k0 + col);
            uint32_t* dst = &As[row * AS_STRIDE + col];
            dst[0] = f2tf32(v.x); dst[1] = f2tf32(v.y);
            dst[2] = f2tf32(v.z); dst[3] = f2tf32(v.w);
        }
        // ---- W1/W3 tiles: 32x128 fp32 -> tf32 ----
#pragma unroll
        for (int i = 0; i < 8; i++) {
            int f = tid + i * 128;
            int row = f >> 5, col = (f & 31) * 4;
            const float4 v1 = *(const float4*)(w1p + (size_t)(k0 + row) * INTER + col);
            const float4 v3 = *(const float4*)(w3p + (size_t)(k0 + row) * INTER + col);
            uint32_t* d1 = &W1s[row * WS_STRIDE + col];
            d1[0] = f2tf32(v1.x); d1[1] = f2tf32(v1.y);
            d1[2] = f2tf32(v1.z); d1[3] = f2tf32(v1.w);
            uint32_t* d3 = &W3s[row * WS_STRIDE + col];
            d3[0] = f2tf32(v3.x); d3[1] = f2tf32(v3.y);
            d3[2] = f2tf32(v3.z); d3[3] = f2tf32(v3.w);
        }
        __syncthreads();

#pragma unroll
        for (int kk = 0; kk < BK; kk += 8) {
            uint32_t a[2][4];
#pragma unroll
            for (int mi = 0; mi < 2; mi++) {
                int rb = wm * 32 + mi * 16;
                a[mi][0] = As[(rb + g)     * AS_STRIDE + kk + tg];
                a[mi][1] = As[(rb + g + 8) * AS_STRIDE + kk + tg];
                a[mi][2] = As[(rb + g)     * AS_STRIDE + kk + tg + 4];
                a[mi][3] = As[(rb + g + 8) * AS_STRIDE + kk + tg + 4];
            }
#pragma unroll
            for (int ni = 0; ni < 8; ni++) {
                int cb = wn * 64 + ni * 8;
                uint32_t b0 = W1s[(kk + tg)     * WS_STRIDE + cb + g];
                uint32_t b1 = W1s[(kk + tg + 4) * WS_STRIDE + cb + g];
                uint32_t c0 = W3s[(kk + tg)     * WS_STRIDE + cb + g];
                uint32_t c1 = W3s[(kk + tg + 4) * WS_STRIDE + cb + g];
                mma_tf32(gacc[0][ni], a[0], b0, b1);
                mma_tf32(gacc[1][ni], a[1], b0, b1);
                mma_tf32(uacc[0][ni], a[0], c0, c1);
                mma_tf32(uacc[1][ni], a[1], c0, c1);
            }
        }
        __syncthreads();
    }

    // ---- epilogue: h = silu(gate)*up -> d_hbuf ----
#pragma unroll
    for (int mi = 0; mi < 2; mi++) {
#pragma unroll
        for (int ni = 0; ni < 8; ni++) {
            int lr0 = wm * 32 + mi * 16 + g;
            int lr1 = lr0 + 8;
            int col = n0 + wn * 64 + ni * 8 + tg * 2;
            if (m0 + lr0 < cnt) {
                float g0 = gacc[mi][ni][0], g1 = gacc[mi][ni][1];
                float h0 = g0 / (1.f + __expf(-g0)) * uacc[mi][ni][0];
                float h1 = g1 / (1.f + __expf(-g1)) * uacc[mi][ni][1];
                *(float2*)(d_hbuf + (size_t)(off + m0 + lr0) * INTER + col) =
                    make_float2(h0, h1);
            }
            if (m0 + lr1 < cnt) {
                float g2 = gacc[mi][ni][2], g3 = gacc[mi][ni][3];
                float h2 = g2 / (1.f + __expf(-g2)) * uacc[mi][ni][2];
                float h3 = g3 / (1.f + __expf(-g3)) * uacc[mi][ni][3];
                *(float2*)(d_hbuf + (size_t)(off + m0 + lr1) * INTER + col) =
                    make_float2(h2, h3);
            }
        }
    }
}

// ---------------------------------------------------------------------------
// GEMM2: y = h @ W2[e]; scatter out[token] += router_weight * y
// ---------------------------------------------------------------------------
__global__ __launch_bounds__(128)
void gemm2_kernel(const float* __restrict__ w2, float* __restrict__ out) {
    const int e   = blockIdx.z;
    const int cnt = d_cnt[e];
    const int m0  = blockIdx.x * BM;
    if (m0 >= cnt) return;
    const int n0  = blockIdx.y * BN;
    const int off = d_off[e];

    __shared__ uint32_t As[BM * AS_STRIDE];
    __shared__ uint32_t Ws[BK * WS_STRIDE];

    const int tid  = threadIdx.x;
    const int lane = tid & 31, warp = tid >> 5;
    const int wm = warp >> 1, wn = warp & 1;
    const int g = lane >> 2, tg = lane & 3;

    const float* aptr[4];
#pragma unroll
    for (int i = 0; i < 4; i++) {
        int f = tid + i * 128;
        int row = f >> 3;
        int gr = m0 + row;
        aptr[i] = (gr < cnt) ? (d_hbuf + (size_t)(off + gr) * INTER) : nullptr;
    }
    const float* wp = w2 + (size_t)e * INTER * HIDDEN + n0;

    float acc[2][8][4];
#pragma unroll
    for (int mi = 0; mi < 2; mi++)
#pragma unroll
        for (int ni = 0; ni < 8; ni++)
#pragma unroll
            for (int r = 0; r < 4; r++) acc[mi][ni][r] = 0.f;

    for (int k0 = 0; k0 < INTER; k0 += BK) {
#pragma unroll
        for (int i = 0; i < 4; i++) {
            int f = tid + i * 128;
            int row = f >> 3, col = (f & 7) * 4;
            float4 v = make_float4(0.f, 0.f, 0.f, 0.f);
            if (aptr[i]) v = *(const float4*)(aptr[i] + k0 + col);
            uint32_t* dst = &As[row * AS_STRIDE + col];
            dst[0] = f2tf32(v.x); dst[1] = f2tf32(v.y);
            dst[2] = f2tf32(v.z); dst[3] = f2tf32(v.w);
        }
#pragma unroll
        for (int i = 0; i < 8; i++) {
            int f = tid + i * 128;
            int row = f >> 5, col = (f & 31) * 4;
            const float4 v = *(const float4*)(wp + (size_t)(k0 + row) * HIDDEN + col);
            uint32_t* dw = &Ws[row * WS_STRIDE + col];
            dw[0] = f2tf32(v.x); dw[1] = f2tf32(v.y);
            dw[2] = f2tf32(v.z); dw[3] = f2tf32(v.w);
        }
        __syncthreads();

#pragma unroll
        for (int kk = 0; kk < BK; kk += 8) {
            uint32_t a[2][4];
#pragma unroll
            for (int mi = 0; mi < 2; mi++) {
                int rb = wm * 32 + mi * 16;
                a[mi][0] = As[(rb + g)     * AS_STRIDE + kk + tg];
                a[mi][1] = As[(rb + g + 8) * AS_STRIDE + kk + tg];
                a[mi][2] = As[(rb + g)     * AS_STRIDE + kk + tg + 4];
                a[mi][3] = As[(rb + g + 8) * AS_STRIDE + kk + tg + 4];
            }
#pragma unroll
            for (int ni = 0; ni < 8; ni++) {
                int cb = wn * 64 + ni * 8;
                uint32_t b0 = Ws[(kk + tg)     * WS_STRIDE + cb + g];
                uint32_t b1 = Ws[(kk + tg + 4) * WS_STRIDE + cb + g];
                mma_tf32(acc[0][ni], a[0], b0, b1);
                mma_tf32(acc[1][ni], a[1], b0, b1);
            }
        }
        __syncthreads();
    }

    // ---- epilogue: out[token] += w * y (top-k combine via atomics) ----
#pragma unroll
    for (int mi = 0; mi < 2; mi++) {
#pragma unroll
        for (int ni = 0; ni < 8; ni++) {
            int lr0 = wm * 32 + mi * 16 + g;
            int lr1 = lr0 + 8;
            int col = n0 + wn * 64 + ni * 8 + tg * 2;
            if (m0 + lr0 < cnt) {
                int   t  = d_tok[off + m0 + lr0];
                float wt = d_wgt[off + m0 + lr0];
                atomicAdd(&out[(size_t)t * HIDDEN + col],     wt * acc[mi][ni][0]);
                atomicAdd(&out[(size_t)t * HIDDEN + col + 1], wt * acc[mi][ni][1]);
            }
            if (m0 + lr1 < cnt) {
                int   t  = d_tok[off + m0 + lr1];
                float wt = d_wgt[off + m0 + lr1];
                atomicAdd(&out[(size_t)t * HIDDEN + col],     wt * acc[mi][ni][2]);
                atomicAdd(&out[(size_t)t * HIDDEN + col + 1], wt * acc[mi][ni][3]);
            }
        }
    }
}

// ---------------------------------------------------------------------------
// launch: route -> gemm1 (gate/up + swiglu) -> gemm2 (+combine)
// inputs (metadata order): x, expert_weights, w1, w2, w3, expert_indices
// ---------------------------------------------------------------------------
extern "C" void kernel_launch(void* const* d_in, const int* in_sizes, int n_in,
                              void* d_out, int out_size) {
    const float* x  = (const float*)d_in[0];
    const float* ew = (const float*)d_in[1];
    const float* w1 = (const float*)d_in[2];
    const float* w2 = (const float*)d_in[3];
    const float* w3 = (const float*)d_in[4];
    const int*   ei = (const int*)d_in[5];
    float* out = (float*)d_out;

    cudaMemsetAsync(out, 0, sizeof(float) * (size_t)TOKENS * HIDDEN, 0);
    route_kernel<<<1, 256>>>(ei, ew);

    dim3 g1(NPAIR / BM, INTER / BN, NEXP);    // m fastest -> L2 W-slab reuse
    gemm1_kernel<<<g1, 128>>>(x, w1, w3);

    dim3 g2(NPAIR / BM, HIDDEN / BN, NEXP);
    gemm2_kernel<<<g2, 128>>>(w2, out);
}

// round 4
// speedup vs baseline: 1.5614x; 1.5614x over previous
#include <cuda_runtime.h>
#include <cstdint>

// Problem constants
#define TOKENS 2048
#define HIDDEN 2048
#define INTER  5632
#define NEXP   8
#define TOPK   2
#define NPAIR  (TOKENS * TOPK)   // 4096

#define BM 128          // token rows per CTA tile
#define BN 128          // output cols per CTA tile
#define BK 32           // K per pipeline chunk (4 tf32 tcgen05 dispatches)
#define NSTG 4          // pipeline stages (tcgen05 path)
#define MAXMT (NPAIR / BM)   // 32 m-slots (worst case: all pairs on one expert)

// tf32 idesc: dtype=f32(1)<<4, atype=tf32(2)<<7, btype=tf32(2)<<10, N/8<<17, M/16<<24
#define IDESC_TF32 ((1u << 4) | (2u << 7) | (2u << 10) | ((BN / 8) << 17) | ((BM / 16) << 24))

// SMEM tile sizes (tf32 = 4B): [128 rows][32 k * 4B = 128B] K-major SW128
#define TILE_BYTES (128 * 128)          // 16 KB per 128-row x 32-k tile
#define G1_STAGE   (3 * TILE_BYTES)     // A + W1 + W3 = 48 KB
#define G2_STAGE   (2 * TILE_BYTES)     // A + W2      = 32 KB
#define SMEM_TMEM  0
#define SMEM_MBAR  16                   // 4 x 8B mbarriers
#define SMEM_DATA  1024
#define G1_SMEM (SMEM_DATA + NSTG * G1_STAGE)   // 197,632 B
#define G2_SMEM (SMEM_DATA + NSTG * G2_STAGE)   // 132,096 B

// Arch-specific feature gate: tcgen05 exists only in the sm_103a pass.
#if defined(__CUDA_ARCH__) && defined(__CUDA_ARCH_FEAT_SM103_ALL)
#define HAS_TCGEN05 1
#else
#define HAS_TCGEN05 0
#endif

// -------- persistent device scratch --------
__device__ int   d_cnt[NEXP];
__device__ int   d_off[NEXP];
__device__ int   d_tok[NPAIR];
__device__ int   d_pos[NPAIR];                                  // pair p -> sorted slot
__device__ float d_hbuf[(size_t)(NPAIR + BM) * INTER];          // padded: safe OOB-row access
__device__ float d_ybuf[(size_t)NPAIR * HIDDEN];                // per-pair gemm2 output

// ---------------------------------------------------------------------------
// common helpers
// ---------------------------------------------------------------------------
__device__ __forceinline__ uint32_t f2tf32(float f) {
    uint32_t u; asm("cvt.rna.tf32.f32 %0, %1;" : "=r"(u) : "f"(f)); return u;
}
__device__ __forceinline__ uint32_t swz128(uint32_t b) { return b ^ ((b >> 3) & 0x70); }

// mma.sync fallback helper (valid on any sm_80+ target)
__device__ __forceinline__ void mma_tf32(float c[4], const uint32_t a[4],
                                         uint32_t b0, uint32_t b1) {
    asm volatile(
        "mma.sync.aligned.m16n8k8.row.col.f32.tf32.tf32.f32 "
        "{%0,%1,%2,%3}, {%4,%5,%6,%7}, {%8,%9}, {%0,%1,%2,%3};\n"
        : "+f"(c[0]), "+f"(c[1]), "+f"(c[2]), "+f"(c[3])
        : "r"(a[0]), "r"(a[1]), "r"(a[2]), "r"(a[3]), "r"(b0), "r"(b1));
}

#if HAS_TCGEN05
__device__ __forceinline__ uint32_t smem_u32(const void* p) {
    uint32_t a;
    asm("{ .reg .u64 t; cvta.to.shared.u64 t, %1; cvt.u32.u64 %0, t; }" : "=r"(a) : "l"(p));
    return a;
}
static __device__ __forceinline__ uint64_t make_desc(uint32_t addr) {
    // K-major SW128: layout=2, version=1, SBO=64 (1024B per 8-row group), LBO=1
    return ((uint64_t)2 << 61) | ((uint64_t)1 << 46) | ((uint64_t)64 << 32) |
           ((uint64_t)1 << 16) | ((uint64_t)(addr >> 4) & 0x3FFF);
}

#define MBAR_INIT(a, c) \
    asm volatile("mbarrier.init.shared.b64 [%0], %1;" :: "r"(a), "r"(c) : "memory")
#define MBAR_WAIT(a, ph) do {                                                     \
    uint32_t _m = (a), _p = (ph), _d;                                             \
    asm volatile("{\n\t.reg .pred p;\n\t"                                         \
        "mbarrier.try_wait.parity.acquire.cta.shared::cta.b64 p, [%1], %2;\n\t"   \
        "selp.b32 %0, 1, 0, p;\n\t}" : "=r"(_d) : "r"(_m), "r"(_p) : "memory");   \
    if (!_d) {                                                                     \
        asm volatile("{\n\t.reg .pred P1;\n\t"                                    \
        "W%=:\n\t"                                                                \
        "mbarrier.try_wait.parity.acquire.cta.shared::cta.b64 P1, [%0], %1, 0x989680;\n\t" \
        "@P1 bra.uni D%=;\n\t bra.uni W%=;\n\t D%=:\n\t}"                        \
        :: "r"(_m), "r"(_p) : "memory");                                          \
    } } while (0)

#define TC_ALLOC(sa, n)  asm volatile("tcgen05.alloc.cta_group::1.sync.aligned.shared::cta.b32 [%0], %1;" :: "r"(sa), "r"(n) : "memory")
#define TC_DEALLOC(t, n) asm volatile("tcgen05.dealloc.cta_group::1.sync.aligned.b32 %0, %1;" :: "r"(t), "r"(n))
#define TC_RELINQ()      asm volatile("tcgen05.relinquish_alloc_permit.cta_group::1.sync.aligned;")
#define TC_COMMIT(a)     asm volatile("tcgen05.commit.cta_group::1.mbarrier::arrive::one.shared::cluster.b64 [%0];" :: "r"(a) : "memory")
#define TC_FENCE_AFTER() asm volatile("tcgen05.fence::after_thread_sync;" ::: "memory")
#define TC_WAIT_LD()     asm volatile("tcgen05.wait::ld.sync.aligned;" ::: "memory")
#define FENCE_ASYNC()    asm volatile("fence.proxy.async.shared::cta;" ::: "memory")

__device__ __forceinline__ void mma_tf32_ss(uint32_t d, uint64_t ad, uint64_t bd,
                                            uint32_t en) {
    asm volatile(
        "{\n\t.reg .pred p;\n\t"
        "setp.ne.u32 p, %4, 0;\n\t"
        "tcgen05.mma.cta_group::1.kind::tf32 [%0], %1, %2, %3, {%5, %5, %5, %5}, p;\n\t"
        "}" :: "r"(d), "l"(ad), "l"(bd), "r"(IDESC_TF32), "r"(en), "r"(0u) : "memory");
}

#define LDTM_X32(r, a)                                                            \
    asm volatile("tcgen05.ld.sync.aligned.32x32b.x32.b32 "                        \
        "{%0,%1,%2,%3,%4,%5,%6,%7,%8,%9,%10,%11,%12,%13,%14,%15,"                 \
        "%16,%17,%18,%19,%20,%21,%22,%23,%24,%25,%26,%27,%28,%29,%30,%31}, [%32];"\
        : "=r"((r)[0]),"=r"((r)[1]),"=r"((r)[2]),"=r"((r)[3]),                    \
          "=r"((r)[4]),"=r"((r)[5]),"=r"((r)[6]),"=r"((r)[7]),                    \
          "=r"((r)[8]),"=r"((r)[9]),"=r"((r)[10]),"=r"((r)[11]),                  \
          "=r"((r)[12]),"=r"((r)[13]),"=r"((r)[14]),"=r"((r)[15]),                \
          "=r"((r)[16]),"=r"((r)[17]),"=r"((r)[18]),"=r"((r)[19]),                \
          "=r"((r)[20]),"=r"((r)[21]),"=r"((r)[22]),"=r"((r)[23]),                \
          "=r"((r)[24]),"=r"((r)[25]),"=r"((r)[26]),"=r"((r)[27]),                \
          "=r"((r)[28]),"=r"((r)[29]),"=r"((r)[30]),"=r"((r)[31]) : "r"(a))

#define STS128(a, q0, q1, q2, q3)                                                 \
    asm volatile("st.shared.v4.b32 [%0], {%1,%2,%3,%4};"                          \
        :: "r"(a), "r"(q0), "r"(q1), "r"(q2), "r"(q3) : "memory")
#endif  // HAS_TCGEN05

// ---------------------------------------------------------------------------
// Routing: bucket 4096 (token, k) pairs by expert; record inverse perm d_pos.
// ---------------------------------------------------------------------------
__global__ void route_kernel(const int* __restrict__ eidx) {
    __shared__ int s_cnt[NEXP], s_off[NEXP], s_cur[NEXP];
    int t = threadIdx.x;
    if (t < NEXP) s_cnt[t] = 0;
    __syncthreads();
    for (int p = t; p < NPAIR; p += blockDim.x) atomicAdd(&s_cnt[eidx[p]], 1);
    __syncthreads();
    if (t == 0) {
        int o = 0;
        for (int e = 0; e < NEXP; e++) { s_off[e] = o; s_cur[e] = o; o += s_cnt[e]; }
    }
    __syncthreads();
    for (int p = t; p < NPAIR; p += blockDim.x) {
        int pos = atomicAdd(&s_cur[eidx[p]], 1);
        d_tok[pos] = p >> 1;
        d_pos[p]   = pos;
    }
    if (t < NEXP) { d_cnt[t] = s_cnt[t]; d_off[t] = s_off[t]; }
}

// ---------------------------------------------------------------------------
// GEMM1: gate = Xg @ W1, up = Xg @ W3, h = silu(gate)*up -> d_hbuf
// ---------------------------------------------------------------------------
__global__ __launch_bounds__(256, 1)
void gemm1_kernel(const float* __restrict__ x,
                  const float* __restrict__ w1g,
                  const float* __restrict__ w3g) {
    const int e    = blockIdx.x >> 5;       // blockIdx.x = e*32 + mslot
    const int cnt  = d_cnt[e];
    const int m0   = (blockIdx.x & 31) * BM;
    if (m0 >= cnt) return;
    const int n0   = blockIdx.y * BN;
    const int off  = d_off[e];
    const int tid = threadIdx.x, wid = tid >> 5, lid = tid & 31;

#if HAS_TCGEN05
    // ======================= tcgen05 tf32 SS path =========================
    extern __shared__ char smem[];
    const uint32_t sb = smem_u32(smem);

    if (wid == 0) TC_ALLOC(sb + SMEM_TMEM, 256);
    if (tid == 0)
        for (int s = 0; s < NSTG; s++) MBAR_INIT(sb + SMEM_MBAR + 8 * s, 1);
    __syncthreads();
    uint32_t tmem;
    asm volatile("ld.shared.b32 %0, [%1];" : "=r"(tmem) : "r"(sb + SMEM_TMEM));
    if (wid == 0) TC_RELINQ();

    // A tasks (4): t = tid + i*256 -> m = t>>3 (row), kq = t&7 (float4 along k)
    const float* xrow[4];
    uint32_t a_sw[4];
#pragma unroll
    for (int i = 0; i < 4; i++) {
        int t = tid + i * 256, m = t >> 3, kq = t & 7;
        int gr = m0 + m;
        int tok = (gr < cnt) ? d_tok[off + gr] : d_tok[off];
        xrow[i] = x + (size_t)tok * HIDDEN + kq * 4;
        a_sw[i] = swz128((uint32_t)(m * 128 + kq * 16));
    }
    // W tasks (4 per matrix): t = tid + i*256 -> kc = t>>7 (0..7), n = t&127
    uint32_t w_sw[4]; size_t w_go[4];
    const float* w1b = w1g + (size_t)e * HIDDEN * INTER + n0;
    const float* w3b = w3g + (size_t)e * HIDDEN * INTER + n0;
#pragma unroll
    for (int i = 0; i < 4; i++) {
        int t = tid + i * 256, kc = t >> 7, n = t & 127;
        w_go[i] = (size_t)(kc * 4) * INTER + n;
        w_sw[i] = swz128((uint32_t)(n * 128 + kc * 16));
    }

    float apf[16], w1pf[16], w3pf[16];
#pragma unroll
    for (int i = 0; i < 4; i++) {
        float4 v = *(const float4*)(xrow[i]);
        apf[4 * i] = v.x; apf[4 * i + 1] = v.y; apf[4 * i + 2] = v.z; apf[4 * i + 3] = v.w;
    }
#pragma unroll
    for (int i = 0; i < 4; i++)
#pragma unroll
        for (int j = 0; j < 4; j++) {
            w1pf[4 * i + j] = w1b[w_go[i] + (size_t)j * INTER];
            w3pf[4 * i + j] = w3b[w_go[i] + (size_t)j * INTER];
        }

    const int NC = HIDDEN / BK;   // 64
    for (int c = 0; c < NC; c++) {
        const int s = c & (NSTG - 1);
        if (c >= NSTG) MBAR_WAIT(sb + SMEM_MBAR + 8 * s, ((c >> 2) - 1) & 1);

        const uint32_t stg = sb + SMEM_DATA + s * G1_STAGE;
#pragma unroll
        for (int i = 0; i < 4; i++)
            STS128(stg + a_sw[i], f2tf32(apf[4 * i]), f2tf32(apf[4 * i + 1]),
                   f2tf32(apf[4 * i + 2]), f2tf32(apf[4 * i + 3]));
#pragma unroll
        for (int i = 0; i < 4; i++) {
            STS128(stg + TILE_BYTES + w_sw[i], f2tf32(w1pf[4 * i]), f2tf32(w1pf[4 * i + 1]),
                   f2tf32(w1pf[4 * i + 2]), f2tf32(w1pf[4 * i + 3]));
            STS128(stg + 2 * TILE_BYTES + w_sw[i], f2tf32(w3pf[4 * i]), f2tf32(w3pf[4 * i + 1]),
                   f2tf32(w3pf[4 * i + 2]), f2tf32(w3pf[4 * i + 3]));
        }
        __syncthreads();

        if (tid == 0) {
            FENCE_ASYNC();
            uint64_t ad = make_desc(stg);
            uint64_t b1 = make_desc(stg + TILE_BYTES);
            uint64_t b3 = make_desc(stg + 2 * TILE_BYTES);
#pragma unroll
            for (int ks = 0; ks < 4; ks++) {
                uint32_t en = (c > 0 || ks > 0) ? 1u : 0u;
                mma_tf32_ss(tmem,       ad + ks * 2, b1 + ks * 2, en);
                mma_tf32_ss(tmem + 128, ad + ks * 2, b3 + ks * 2, en);
            }
            TC_COMMIT(sb + SMEM_MBAR + 8 * s);
        }

        if (c + 1 < NC) {
            const int k0 = (c + 1) * BK;
#pragma unroll
            for (int i = 0; i < 4; i++) {
                float4 v = *(const float4*)(xrow[i] + k0);
                apf[4 * i] = v.x; apf[4 * i + 1] = v.y;
                apf[4 * i + 2] = v.z; apf[4 * i + 3] = v.w;
            }
#pragma unroll
            for (int i = 0; i < 4; i++) {
                size_t go = w_go[i] + (size_t)k0 * INTER;
#pragma unroll
                for (int j = 0; j < 4; j++) {
                    w1pf[4 * i + j] = w1b[go + (size_t)j * INTER];
                    w3pf[4 * i + j] = w3b[go + (size_t)j * INTER];
                }
            }
        }
    }

    MBAR_WAIT(sb + SMEM_MBAR + 8 * ((NC - 1) & 3), ((NC - 1) >> 2) & 1);
    TC_FENCE_AFTER();
    if (wid < 4) {
        const int mr = wid * 32 + lid;
        const bool ok = (m0 + mr) < cnt;
        float* hrow = d_hbuf + (size_t)(off + m0 + mr) * INTER + n0;
#pragma unroll
        for (int cb = 0; cb < 128; cb += 32) {
            uint32_t gr[32], ur[32];
            LDTM_X32(gr, tmem + cb);
            LDTM_X32(ur, tmem + 128 + cb);
            TC_WAIT_LD();
            if (ok) {
#pragma unroll
                for (int j = 0; j < 32; j += 4) {
                    float4 hv;
                    float g0 = __uint_as_float(gr[j]);
                    float g1 = __uint_as_float(gr[j + 1]);
                    float g2 = __uint_as_float(gr[j + 2]);
                    float g3 = __uint_as_float(gr[j + 3]);
                    hv.x = g0 / (1.f + __expf(-g0)) * __uint_as_float(ur[j]);
                    hv.y = g1 / (1.f + __expf(-g1)) * __uint_as_float(ur[j + 1]);
                    hv.z = g2 / (1.f + __expf(-g2)) * __uint_as_float(ur[j + 2]);
                    hv.w = g3 / (1.f + __expf(-g3)) * __uint_as_float(ur[j + 3]);
                    *(float4*)(hrow + cb + j) = hv;
                }
            }
        }
    }
    __syncthreads();
    if (wid == 0) TC_DEALLOC(tmem, 256);

#else
    // ================= mma.sync fallback (non-103a pass) ==================
    extern __shared__ char smem_raw[];
    uint32_t* As  = (uint32_t*)smem_raw;         // 128 x 36
    uint32_t* W1s = As + 128 * 36;               // 32 x 136
    uint32_t* W3s = W1s + 32 * 136;

    const int half = wid >> 2;                   // 0: rows 0-63, 1: rows 64-127
    const int w4 = wid & 3, wm = w4 >> 1, wn = w4 & 1;
    const int g = lid >> 2, tg = lid & 3;

    const float* aptr[4];
#pragma unroll
    for (int i = 0; i < 4; i++) {
        int f = tid + i * 256, row = f >> 3;
        int gr = m0 + row;
        aptr[i] = (gr < cnt) ? (x + (size_t)d_tok[off + gr] * HIDDEN) : nullptr;
    }
    const float* w1p = w1g + (size_t)e * HIDDEN * INTER + n0;
    const float* w3p = w3g + (size_t)e * HIDDEN * INTER + n0;

    float gacc[2][8][4], uacc[2][8][4];
#pragma unroll
    for (int mi = 0; mi < 2; mi++)
#pragma unroll
        for (int ni = 0; ni < 8; ni++)
#pragma unroll
            for (int r = 0; r < 4; r++) { gacc[mi][ni][r] = 0.f; uacc[mi][ni][r] = 0.f; }

    for (int k0 = 0; k0 < HIDDEN; k0 += BK) {
#pragma unroll
        for (int i = 0; i < 4; i++) {
            int f = tid + i * 256, row = f >> 3, col = (f & 7) * 4;
            float4 v = make_float4(0.f, 0.f, 0.f, 0.f);
            if (aptr[i]) v = *(const float4*)(aptr[i] + k0 + col);
            uint32_t* dst = &As[row * 36 + col];
            dst[0] = f2tf32(v.x); dst[1] = f2tf32(v.y);
            dst[2] = f2tf32(v.z); dst[3] = f2tf32(v.w);
        }
#pragma unroll
        for (int i = 0; i < 4; i++) {
            int f = tid + i * 256, row = f >> 5, col = (f & 31) * 4;
            const float4 v1 = *(const float4*)(w1p + (size_t)(k0 + row) * INTER + col);
            const float4 v3 = *(const float4*)(w3p + (size_t)(k0 + row) * INTER + col);
            uint32_t* d1 = &W1s[row * 136 + col];
            d1[0] = f2tf32(v1.x); d1[1] = f2tf32(v1.y);
            d1[2] = f2tf32(v1.z); d1[3] = f2tf32(v1.w);
            uint32_t* d3 = &W3s[row * 136 + col];
            d3[0] = f2tf32(v3.x); d3[1] = f2tf32(v3.y);
            d3[2] = f2tf32(v3.z); d3[3] = f2tf32(v3.w);
        }
        __syncthreads();

#pragma unroll
        for (int kk = 0; kk < BK; kk += 8) {
            uint32_t a[2][4];
#pragma unroll
            for (int mi = 0; mi < 2; mi++) {
                int rb = half * 64 + wm * 32 + mi * 16;
                a[mi][0] = As[(rb + g)     * 36 + kk + tg];
                a[mi][1] = As[(rb + g + 8) * 36 + kk + tg];
                a[mi][2] = As[(rb + g)     * 36 + kk + tg + 4];
                a[mi][3] = As[(rb + g + 8) * 36 + kk + tg + 4];
            }
#pragma unroll
            for (int ni = 0; ni < 8; ni++) {
                int cb = wn * 64 + ni * 8;
                uint32_t b0 = W1s[(kk + tg)     * 136 + cb + g];
                uint32_t b1 = W1s[(kk + tg + 4) * 136 + cb + g];
                uint32_t c0 = W3s[(kk + tg)     * 136 + cb + g];
                uint32_t c1 = W3s[(kk + tg + 4) * 136 + cb + g];
                mma_tf32(gacc[0][ni], a[0], b0, b1);
                mma_tf32(gacc[1][ni], a[1], b0, b1);
                mma_tf32(uacc[0][ni], a[0], c0, c1);
                mma_tf32(uacc[1][ni], a[1], c0, c1);
            }
        }
        __syncthreads();
    }

#pragma unroll
    for (int mi = 0; mi < 2; mi++) {
#pragma unroll
        for (int ni = 0; ni < 8; ni++) {
            int lr0 = half * 64 + wm * 32 + mi * 16 + g;
            int lr1 = lr0 + 8;
            int col = n0 + wn * 64 + ni * 8 + tg * 2;
            if (m0 + lr0 < cnt) {
                float g0 = gacc[mi][ni][0], g1 = gacc[mi][ni][1];
                float h0 = g0 / (1.f + __expf(-g0)) * uacc[mi][ni][0];
                float h1 = g1 / (1.f + __expf(-g1)) * uacc[mi][ni][1];
                *(float2*)(d_hbuf + (size_t)(off + m0 + lr0) * INTER + col) =
                    make_float2(h0, h1);
            }
            if (m0 + lr1 < cnt) {
                float g2 = gacc[mi][ni][2], g3 = gacc[mi][ni][3];
                float h2 = g2 / (1.f + __expf(-g2)) * uacc[mi][ni][2];
                float h3 = g3 / (1.f + __expf(-g3)) * uacc[mi][ni][3];
                *(float2*)(d_hbuf + (size_t)(off + m0 + lr1) * INTER + col) =
                    make_float2(h2, h3);
            }
        }
    }
#endif
}

// ---------------------------------------------------------------------------
// GEMM2: y = h @ W2 -> d_ybuf (per sorted pair row)
// ---------------------------------------------------------------------------
__global__ __launch_bounds__(256, 1)
void gemm2_kernel(const float* __restrict__ w2g) {
    const int e    = blockIdx.x >> 5;
    const int cnt  = d_cnt[e];
    const int m0   = (blockIdx.x & 31) * BM;
    if (m0 >= cnt) return;
    const int n0   = blockIdx.y * BN;
    const int off  = d_off[e];
    const int tid = threadIdx.x, wid = tid >> 5, lid = tid & 31;

#if HAS_TCGEN05
    extern __shared__ char smem[];
    const uint32_t sb = smem_u32(smem);

    if (wid == 0) TC_ALLOC(sb + SMEM_TMEM, 128);
    if (tid == 0)
        for (int s = 0; s < NSTG; s++) MBAR_INIT(sb + SMEM_MBAR + 8 * s, 1);
    __syncthreads();
    uint32_t tmem;
    asm volatile("ld.shared.b32 %0, [%1];" : "=r"(tmem) : "r"(sb + SMEM_TMEM));
    if (wid == 0) TC_RELINQ();

    const float* arow[4];
    uint32_t a_sw[4];
#pragma unroll
    for (int i = 0; i < 4; i++) {
        int t = tid + i * 256, m = t >> 3, kq = t & 7;
        arow[i] = d_hbuf + (size_t)(off + m0 + m) * INTER + kq * 4;  // padded buffer
        a_sw[i] = swz128((uint32_t)(m * 128 + kq * 16));
    }
    uint32_t w_sw[4]; size_t w_go[4];
    const float* w2b = w2g + (size_t)e * INTER * HIDDEN + n0;
#pragma unroll
    for (int i = 0; i < 4; i++) {
        int t = tid + i * 256, kc = t >> 7, n = t & 127;
        w_go[i] = (size_t)(kc * 4) * HIDDEN + n;
        w_sw[i] = swz128((uint32_t)(n * 128 + kc * 16));
    }

    float apf[16], wpf[16];
#pragma unroll
    for (int i = 0; i < 4; i++) {
        float4 v = *(const float4*)(arow[i]);
        apf[4 * i] = v.x; apf[4 * i + 1] = v.y; apf[4 * i + 2] = v.z; apf[4 * i + 3] = v.w;
    }
#pragma unroll
    for (int i = 0; i < 4; i++)
#pragma unroll
        for (int j = 0; j < 4; j++) wpf[4 * i + j] = w2b[w_go[i] + (size_t)j * HIDDEN];

    const int NC = INTER / BK;   // 176
    for (int c = 0; c < NC; c++) {
        const int s = c & (NSTG - 1);
        if (c >= NSTG) MBAR_WAIT(sb + SMEM_MBAR + 8 * s, ((c >> 2) - 1) & 1);

        const uint32_t stg = sb + SMEM_DATA + s * G2_STAGE;
#pragma unroll
        for (int i = 0; i < 4; i++)
            STS128(stg + a_sw[i], f2tf32(apf[4 * i]), f2tf32(apf[4 * i + 1]),
                   f2tf32(apf[4 * i + 2]), f2tf32(apf[4 * i + 3]));
#pragma unroll
        for (int i = 0; i < 4; i++)
            STS128(stg + TILE_BYTES + w_sw[i], f2tf32(wpf[4 * i]), f2tf32(wpf[4 * i + 1]),
                   f2tf32(wpf[4 * i + 2]), f2tf32(wpf[4 * i + 3]));
        __syncthreads();

        if (tid == 0) {
            FENCE_ASYNC();
            uint64_t ad = make_desc(stg);
            uint64_t bd = make_desc(stg + TILE_BYTES);
#pragma unroll
            for (int ks = 0; ks < 4; ks++)
                mma_tf32_ss(tmem, ad + ks * 2, bd + ks * 2, (c > 0 || ks > 0) ? 1u : 0u);
            TC_COMMIT(sb + SMEM_MBAR + 8 * s);
        }

        if (c + 1 < NC) {
            const int k0 = (c + 1) * BK;
#pragma unroll
            for (int i = 0; i < 4; i++) {
                float4 v = *(const float4*)(arow[i] + k0);
                apf[4 * i] = v.x; apf[4 * i + 1] = v.y;
                apf[4 * i + 2] = v.z; apf[4 * i + 3] = v.w;
            }
#pragma unroll
            for (int i = 0; i < 4; i++) {
                size_t go = w_go[i] + (size_t)k0 * HIDDEN;
#pragma unroll
                for (int j = 0; j < 4; j++) wpf[4 * i + j] = w2b[go + (size_t)j * HIDDEN];
            }
        }
    }

    MBAR_WAIT(sb + SMEM_MBAR + 8 * ((NC - 1) & 3), ((NC - 1) >> 2) & 1);
    TC_FENCE_AFTER();
    if (wid < 4) {
        const int mr = wid * 32 + lid;
        const bool ok = (m0 + mr) < cnt;      // per-lane; LDTM stays collective
        float* yrow = d_ybuf + (size_t)(off + m0 + mr) * HIDDEN + n0;
#pragma unroll
        for (int cb = 0; cb < 128; cb += 32) {
            uint32_t yr[32];
            LDTM_X32(yr, tmem + cb);
            TC_WAIT_LD();
            if (ok) {
#pragma unroll
                for (int j = 0; j < 32; j += 4) {
                    float4 v;
                    v.x = __uint_as_float(yr[j]);     v.y = __uint_as_float(yr[j + 1]);
                    v.z = __uint_as_float(yr[j + 2]); v.w = __uint_as_float(yr[j + 3]);
                    *(float4*)(yrow + cb + j) = v;
                }
            }
        }
    }
    __syncthreads();
    if (wid == 0) TC_DEALLOC(tmem, 128);

#else
    // ================= mma.sync fallback ==================
    extern __shared__ char smem_raw[];
    uint32_t* As = (uint32_t*)smem_raw;          // 128 x 36
    uint32_t* Ws = As + 128 * 36;                // 32 x 136

    const int half = wid >> 2;
    const int w4 = wid & 3, wm = w4 >> 1, wn = w4 & 1;
    const int g = lid >> 2, tg = lid & 3;

    const float* aptr[4];
#pragma unroll
    for (int i = 0; i < 4; i++) {
        int f = tid + i * 256, row = f >> 3;
        aptr[i] = d_hbuf + (size_t)(off + m0 + row) * INTER;   // padded buffer
    }
    const float* wp = w2g + (size_t)e * INTER * HIDDEN + n0;

    float acc[2][8][4];
#pragma unroll
    for (int mi = 0; mi < 2; mi++)
#pragma unroll
        for (int ni = 0; ni < 8; ni++)
#pragma unroll
            for (int r = 0; r < 4; r++) acc[mi][ni][r] = 0.f;

    for (int k0 = 0; k0 < INTER; k0 += BK) {
#pragma unroll
        for (int i = 0; i < 4; i++) {
            int f = tid + i * 256, row = f >> 3, col = (f & 7) * 4;
            float4 v = *(const float4*)(aptr[i] + k0 + col);
            uint32_t* dst = &As[row * 36 + col];
            dst[0] = f2tf32(v.x); dst[1] = f2tf32(v.y);
            dst[2] = f2tf32(v.z); dst[3] = f2tf32(v.w);
        }
#pragma unroll
        for (int i = 0; i < 4; i++) {
            int f = tid + i * 256, row = f >> 5, col = (f & 31) * 4;
            const float4 v = *(const float4*)(wp + (size_t)(k0 + row) * HIDDEN + col);
            uint32_t* dw = &Ws[row * 136 + col];
            dw[0] = f2tf32(v.x); dw[1] = f2tf32(v.y);
            dw[2] = f2tf32(v.z); dw[3] = f2tf32(v.w);
        }
        __syncthreads();

#pragma unroll
        for (int kk = 0; kk < BK; kk += 8) {
            uint32_t a[2][4];
#pragma unroll
            for (int mi = 0; mi < 2; mi++) {
                int rb = half * 64 + wm * 32 + mi * 16;
                a[mi][0] = As[(rb + g)     * 36 + kk + tg];
                a[mi][1] = As[(rb + g + 8) * 36 + kk + tg];
                a[mi][2] = As[(rb + g)     * 36 + kk + tg + 4];
                a[mi][3] = As[(rb + g + 8) * 36 + kk + tg + 4];
            }
#pragma unroll
            for (int ni = 0; ni < 8; ni++) {
                int cb = wn * 64 + ni * 8;
                uint32_t b0 = Ws[(kk + tg)     * 136 + cb + g];
                uint32_t b1 = Ws[(kk + tg + 4) * 136 + cb + g];
                mma_tf32(acc[0][ni], a[0], b0, b1);
                mma_tf32(acc[1][ni], a[1], b0, b1);
            }
        }
        __syncthreads();
    }

#pragma unroll
    for (int mi = 0; mi < 2; mi++) {
#pragma unroll
        for (int ni = 0; ni < 8; ni++) {
            int lr0 = half * 64 + wm * 32 + mi * 16 + g;
            int lr1 = lr0 + 8;
            int col = n0 + wn * 64 + ni * 8 + tg * 2;
            if (m0 + lr0 < cnt)
                *(float2*)(d_ybuf + (size_t)(off + m0 + lr0) * HIDDEN + col) =
                    make_float2(acc[mi][ni][0], acc[mi][ni][1]);
            if (m0 + lr1 < cnt)
                *(float2*)(d_ybuf + (size_t)(off + m0 + lr1) * HIDDEN + col) =
                    make_float2(acc[mi][ni][2], acc[mi][ni][3]);
        }
    }
#endif
}

// ---------------------------------------------------------------------------
// Combine: out[t] = ew[2t]*y[pos[2t]] + ew[2t+1]*y[pos[2t+1]]
// ---------------------------------------------------------------------------
__global__ __launch_bounds__(256)
void combine_kernel(const float* __restrict__ ew, float* __restrict__ out) {
    const int t = blockIdx.x;
    const int p0 = d_pos[2 * t], p1 = d_pos[2 * t + 1];
    const float w0 = ew[2 * t], w1 = ew[2 * t + 1];
    const float4* y0 = (const float4*)(d_ybuf + (size_t)p0 * HIDDEN);
    const float4* y1 = (const float4*)(d_ybuf + (size_t)p1 * HIDDEN);
    float4* o = (float4*)(out + (size_t)t * HIDDEN);
#pragma unroll
    for (int i = threadIdx.x; i < HIDDEN / 4; i += 256) {
        float4 a = y0[i], b = y1[i], r;
        r.x = w0 * a.x + w1 * b.x; r.y = w0 * a.y + w1 * b.y;
        r.z = w0 * a.z + w1 * b.z; r.w = w0 * a.w + w1 * b.w;
        o[i] = r;
    }
}

// ---------------------------------------------------------------------------
// launch
// inputs (metadata order): x, expert_weights, w1, w2, w3, expert_indices
// ---------------------------------------------------------------------------
extern "C" void kernel_launch(void* const* d_in, const int* in_sizes, int n_in,
                              void* d_out, int out_size) {
    const float* x  = (const float*)d_in[0];
    const float* ew = (const float*)d_in[1];
    const float* w1 = (const float*)d_in[2];
    const float* w2 = (const float*)d_in[3];
    const float* w3 = (const float*)d_in[4];
    const int*   ei = (const int*)d_in[5];
    float* out = (float*)d_out;

    static int attr_done = 0;
    if (!attr_done) {
        cudaFuncSetAttribute(gemm1_kernel, cudaFuncAttributeMaxDynamicSharedMemorySize, G1_SMEM);
        cudaFuncSetAttribute(gemm2_kernel, cudaFuncAttributeMaxDynamicSharedMemorySize, G2_SMEM);
        attr_done = 1;
    }

    route_kernel<<<1, 256>>>(ei);

    dim3 g1(NEXP * MAXMT, INTER / BN);   // 256 x 44 (empty m-slots exit early)
    gemm1_kernel<<<g1, 256, G1_SMEM>>>(x, w1, w3);

    dim3 g2(NEXP * MAXMT, HIDDEN / BN);  // 256 x 16
    gemm2_kernel<<<g2, 256, G2_SMEM>>>(w2);

    combine_kernel<<<TOKENS, 256>>>(ew, out);
}

// round 5
// speedup vs baseline: 2.6588x; 1.7028x over previous
#include <cuda_runtime.h>
#include <cuda_fp16.h>
#include <cstdint>

// Problem constants
#define TOKENS 2048
#define HIDDEN 2048
#define INTER  5632
#define NEXP   8
#define TOPK   2
#define NPAIR  (TOKENS * TOPK)   // 4096

#define BM 128            // token rows per CTA tile
#define BN 128            // output cols per CTA tile
#define MAXMT (NPAIR / BM)   // 32 m-slots

// ---- tcgen05 path config (fp16, K-major SW128, BK=64) ----
#define BK_TC 64
#define NSTG  4
#define TILE_BYTES (128 * 128)          // 128 rows x 128B (64 fp16) = 16 KB
#define G1_STAGE   (3 * TILE_BYTES)     // A + W1 + W3 = 48 KB
#define G2_STAGE   (2 * TILE_BYTES)     // A + W2      = 32 KB
#define SMEM_TMEM  0
#define SMEM_MBAR  16
#define SMEM_DATA  1024
#define G1_SMEM (SMEM_DATA + NSTG * G1_STAGE)   // 197,632 B
#define G2_SMEM (SMEM_DATA + NSTG * G2_STAGE)   // 132,096 B

// fp16 idesc: dtype=f32(1)<<4, atype=f16(0), btype=f16(0), N/8<<17, M/16<<24
#define IDESC_F16 ((1u << 4) | ((BN / 8) << 17) | ((BM / 16) << 24))

// ---- fallback path config (mma.sync m16n8k16, BK=32, double-buffered) ----
#define FBK 32
#define SSTR 20                         // smem row stride in uint32 (16 used + 4 pad)
#define G1_FB_WORDS (3 * 128 * SSTR)    // A + W1 + W3 per buffer
#define G2_FB_WORDS (2 * 128 * SSTR)

#if defined(__CUDA_ARCH__) && defined(__CUDA_ARCH_FEAT_SM103_ALL)
#define HAS_TCGEN05 1
#else
#define HAS_TCGEN05 0
#endif

// -------- persistent device scratch --------
__device__ int      d_cnt[NEXP];
__device__ int      d_off[NEXP];
__device__ int      d_tok[NPAIR];
__device__ int      d_pos[NPAIR];
// h stored as packed fp16 pairs (halves gemm2 A traffic); padded rows for OOB
__device__ uint32_t d_hbuf[(size_t)(NPAIR + BM) * (INTER / 2)];
__device__ float    d_ybuf[(size_t)NPAIR * HIDDEN];

// ---------------------------------------------------------------------------
// common helpers
// ---------------------------------------------------------------------------
__device__ __forceinline__ uint32_t packh2(float lo, float hi) {
    __half2 h = __floats2half2_rn(lo, hi);
    return *reinterpret_cast<uint32_t*>(&h);
}
__device__ __forceinline__ uint32_t swz128(uint32_t b) { return b ^ ((b >> 3) & 0x70); }

// fp16 mma with fp32 accum (any sm_80+ target)
__device__ __forceinline__ void mma16816(float c[4], const uint32_t a[4],
                                         uint32_t b0, uint32_t b1) {
    asm volatile(
        "mma.sync.aligned.m16n8k16.row.col.f32.f16.f16.f32 "
        "{%0,%1,%2,%3}, {%4,%5,%6,%7}, {%8,%9}, {%0,%1,%2,%3};\n"
        : "+f"(c[0]), "+f"(c[1]), "+f"(c[2]), "+f"(c[3])
        : "r"(a[0]), "r"(a[1]), "r"(a[2]), "r"(a[3]), "r"(b0), "r"(b1));
}

#define STS128(a, q0, q1, q2, q3)                                                 \
    asm volatile("st.shared.v4.b32 [%0], {%1,%2,%3,%4};"                          \
        :: "r"(a), "r"(q0), "r"(q1), "r"(q2), "r"(q3) : "memory")

#if HAS_TCGEN05
__device__ __forceinline__ uint32_t smem_u32(const void* p) {
    uint32_t a;
    asm("{ .reg .u64 t; cvta.to.shared.u64 t, %1; cvt.u32.u64 %0, t; }" : "=r"(a) : "l"(p));
    return a;
}
static __device__ __forceinline__ uint64_t make_desc(uint32_t addr) {
    // K-major SW128: layout=2, version=1, SBO=64, LBO=1
    return ((uint64_t)2 << 61) | ((uint64_t)1 << 46) | ((uint64_t)64 << 32) |
           ((uint64_t)1 << 16) | ((uint64_t)(addr >> 4) & 0x3FFF);
}

#define MBAR_INIT(a, c) \
    asm volatile("mbarrier.init.shared.b64 [%0], %1;" :: "r"(a), "r"(c) : "memory")
#define MBAR_WAIT(a, ph) do {                                                     \
    uint32_t _m = (a), _p = (ph), _d;                                             \
    asm volatile("{\n\t.reg .pred p;\n\t"                                         \
        "mbarrier.try_wait.parity.acquire.cta.shared::cta.b64 p, [%1], %2;\n\t"   \
        "selp.b32 %0, 1, 0, p;\n\t}" : "=r"(_d) : "r"(_m), "r"(_p) : "memory");   \
    if (!_d) {                                                                     \
        asm volatile("{\n\t.reg .pred P1;\n\t"                                    \
        "W%=:\n\t"                                                                \
        "mbarrier.try_wait.parity.acquire.cta.shared::cta.b64 P1, [%0], %1, 0x989680;\n\t" \
        "@P1 bra.uni D%=;\n\t bra.uni W%=;\n\t D%=:\n\t}"                        \
        :: "r"(_m), "r"(_p) : "memory");                                          \
    } } while (0)

#define TC_ALLOC(sa, n)  asm volatile("tcgen05.alloc.cta_group::1.sync.aligned.shared::cta.b32 [%0], %1;" :: "r"(sa), "r"(n) : "memory")
#define TC_DEALLOC(t, n) asm volatile("tcgen05.dealloc.cta_group::1.sync.aligned.b32 %0, %1;" :: "r"(t), "r"(n))
#define TC_RELINQ()      asm volatile("tcgen05.relinquish_alloc_permit.cta_group::1.sync.aligned;")
#define TC_COMMIT(a)     asm volatile("tcgen05.commit.cta_group::1.mbarrier::arrive::one.shared::cluster.b64 [%0];" :: "r"(a) : "memory")
#define TC_FENCE_AFTER() asm volatile("tcgen05.fence::after_thread_sync;" ::: "memory")
#define TC_WAIT_LD()     asm volatile("tcgen05.wait::ld.sync.aligned;" ::: "memory")
#define FENCE_ASYNC()    asm volatile("fence.proxy.async.shared::cta;" ::: "memory")

__device__ __forceinline__ void mma_f16_ss(uint32_t d, uint64_t ad, uint64_t bd,
                                           uint32_t en) {
    asm volatile(
        "{\n\t.reg .pred p;\n\t"
        "setp.ne.u32 p, %4, 0;\n\t"
        "tcgen05.mma.cta_group::1.kind::f16 [%0], %1, %2, %3, {%5, %5, %5, %5}, p;\n\t"
        "}" :: "r"(d), "l"(ad), "l"(bd), "r"(IDESC_F16), "r"(en), "r"(0u) : "memory");
}

#define LDTM_X32(r, a)                                                            \
    asm volatile("tcgen05.ld.sync.aligned.32x32b.x32.b32 "                        \
        "{%0,%1,%2,%3,%4,%5,%6,%7,%8,%9,%10,%11,%12,%13,%14,%15,"                 \
        "%16,%17,%18,%19,%20,%21,%22,%23,%24,%25,%26,%27,%28,%29,%30,%31}, [%32];"\
        : "=r"((r)[0]),"=r"((r)[1]),"=r"((r)[2]),"=r"((r)[3]),                    \
          "=r"((r)[4]),"=r"((r)[5]),"=r"((r)[6]),"=r"((r)[7]),                    \
          "=r"((r)[8]),"=r"((r)[9]),"=r"((r)[10]),"=r"((r)[11]),                  \
          "=r"((r)[12]),"=r"((r)[13]),"=r"((r)[14]),"=r"((r)[15]),                \
          "=r"((r)[16]),"=r"((r)[17]),"=r"((r)[18]),"=r"((r)[19]),                \
          "=r"((r)[20]),"=r"((r)[21]),"=r"((r)[22]),"=r"((r)[23]),                \
          "=r"((r)[24]),"=r"((r)[25]),"=r"((r)[26]),"=r"((r)[27]),                \
          "=r"((r)[28]),"=r"((r)[29]),"=r"((r)[30]),"=r"((r)[31]) : "r"(a))
#endif  // HAS_TCGEN05

// ---------------------------------------------------------------------------
// Routing
// ---------------------------------------------------------------------------
__global__ void route_kernel(const int* __restrict__ eidx) {
    __shared__ int s_cnt[NEXP], s_off[NEXP], s_cur[NEXP];
    int t = threadIdx.x;
    if (t < NEXP) s_cnt[t] = 0;
    __syncthreads();
    for (int p = t; p < NPAIR; p += blockDim.x) atomicAdd(&s_cnt[eidx[p]], 1);
    __syncthreads();
    if (t == 0) {
        int o = 0;
        for (int e = 0; e < NEXP; e++) { s_off[e] = o; s_cur[e] = o; o += s_cnt[e]; }
    }
    __syncthreads();
    for (int p = t; p < NPAIR; p += blockDim.x) {
        int pos = atomicAdd(&s_cur[eidx[p]], 1);
        d_tok[pos] = p >> 1;
        d_pos[p]   = pos;
    }
    if (t < NEXP) { d_cnt[t] = s_cnt[t]; d_off[t] = s_off[t]; }
}

// ---------------------------------------------------------------------------
// GEMM1: gate = Xg @ W1, up = Xg @ W3, h = silu(gate)*up -> d_hbuf (fp16 packed)
// ---------------------------------------------------------------------------
__global__ __launch_bounds__(512, 1)
void gemm1_kernel(const float* __restrict__ x,
                  const float* __restrict__ w1g,
                  const float* __restrict__ w3g) {
    const int e    = blockIdx.x >> 5;
    const int cnt  = d_cnt[e];
    const int m0   = (blockIdx.x & 31) * BM;
    if (m0 >= cnt) return;
    const int n0   = blockIdx.y * BN;
    const int off  = d_off[e];
    const int tid = threadIdx.x, wid = tid >> 5, lid = tid & 31;
    const int g = lid >> 2, tg = lid & 3;

    const float* w1b = w1g + (size_t)e * HIDDEN * INTER + n0;
    const float* w3b = w3g + (size_t)e * HIDDEN * INTER + n0;

#if HAS_TCGEN05
    // ======================= tcgen05 fp16 SS path =========================
    extern __shared__ char smem[];
    const uint32_t sb = smem_u32(smem);

    if (wid == 0) TC_ALLOC(sb + SMEM_TMEM, 256);
    if (tid == 0)
        for (int s = 0; s < NSTG; s++) MBAR_INIT(sb + SMEM_MBAR + 8 * s, 1);
    __syncthreads();
    uint32_t tmem;
    asm volatile("ld.shared.b32 %0, [%1];" : "=r"(tmem) : "r"(sb + SMEM_TMEM));
    if (wid == 0) TC_RELINQ();

    // A tasks (2): t = tid + i*512 -> m = t>>3, kb = t&7 (8 fp16 = 16B block)
    const float* xr[2]; uint32_t a_sw[2];
#pragma unroll
    for (int i = 0; i < 2; i++) {
        int t = tid + i * 512, m = t >> 3, kb = t & 7;
        int tok = (m0 + m < cnt) ? d_tok[off + m0 + m] : d_tok[off];
        xr[i]   = x + (size_t)tok * HIDDEN + kb * 8;
        a_sw[i] = swz128((uint32_t)(m * 128 + kb * 16));
    }
    // W tasks (2 per matrix): t -> n = t&127, kb = t>>7
    const float *w1t[2], *w3t[2]; uint32_t w_sw[2];
#pragma unroll
    for (int i = 0; i < 2; i++) {
        int t = tid + i * 512, n = t & 127, kb = t >> 7;
        w1t[i] = w1b + (size_t)(kb * 8) * INTER + n;
        w3t[i] = w3b + (size_t)(kb * 8) * INTER + n;
        w_sw[i] = swz128((uint32_t)(n * 128 + kb * 16));
    }

    uint32_t apf[8], w1pf[8], w3pf[8];
    auto prefetch = [&](int k0) {
#pragma unroll
        for (int i = 0; i < 2; i++) {
            float4 v0 = *(const float4*)(xr[i] + k0);
            float4 v1 = *(const float4*)(xr[i] + k0 + 4);
            apf[4*i]   = packh2(v0.x, v0.y); apf[4*i+1] = packh2(v0.z, v0.w);
            apf[4*i+2] = packh2(v1.x, v1.y); apf[4*i+3] = packh2(v1.z, v1.w);
        }
#pragma unroll
        for (int i = 0; i < 2; i++) {
            float t1[8], t3[8];
#pragma unroll
            for (int j = 0; j < 8; j++) {
                t1[j] = w1t[i][(size_t)(k0 + j) * INTER];
                t3[j] = w3t[i][(size_t)(k0 + j) * INTER];
            }
#pragma unroll
            for (int j = 0; j < 4; j++) {
                w1pf[4*i+j] = packh2(t1[2*j], t1[2*j+1]);
                w3pf[4*i+j] = packh2(t3[2*j], t3[2*j+1]);
            }
        }
    };

    prefetch(0);
    const int NC = HIDDEN / BK_TC;   // 32
    for (int c = 0; c < NC; c++) {
        const int s = c & (NSTG - 1);
        if (c >= NSTG) MBAR_WAIT(sb + SMEM_MBAR + 8 * s, ((c >> 2) - 1) & 1);

        const uint32_t stg = sb + SMEM_DATA + s * G1_STAGE;
#pragma unroll
        for (int i = 0; i < 2; i++) {
            STS128(stg + a_sw[i], apf[4*i], apf[4*i+1], apf[4*i+2], apf[4*i+3]);
            STS128(stg + TILE_BYTES + w_sw[i], w1pf[4*i], w1pf[4*i+1], w1pf[4*i+2], w1pf[4*i+3]);
            STS128(stg + 2*TILE_BYTES + w_sw[i], w3pf[4*i], w3pf[4*i+1], w3pf[4*i+2], w3pf[4*i+3]);
        }
        __syncthreads();

        if (tid == 0) {
            FENCE_ASYNC();
            uint64_t ad = make_desc(stg);
            uint64_t b1 = make_desc(stg + TILE_BYTES);
            uint64_t b3 = make_desc(stg + 2*TILE_BYTES);
#pragma unroll
            for (int ks = 0; ks < 4; ks++) {      // K=16 per dispatch
                uint32_t en = (c > 0 || ks > 0) ? 1u : 0u;
                mma_f16_ss(tmem,       ad + ks * 2, b1 + ks * 2, en);
                mma_f16_ss(tmem + 128, ad + ks * 2, b3 + ks * 2, en);
            }
            TC_COMMIT(sb + SMEM_MBAR + 8 * s);
        }
        if (c + 1 < NC) prefetch((c + 1) * BK_TC);
    }

    MBAR_WAIT(sb + SMEM_MBAR + 8 * ((NC - 1) & 3), ((NC - 1) >> 2) & 1);
    TC_FENCE_AFTER();
    if (wid < 4) {
        const int mr = wid * 32 + lid;
        const bool ok = (m0 + mr) < cnt;
        uint32_t* hrow = d_hbuf + (size_t)(off + m0 + mr) * (INTER / 2) + n0 / 2;
#pragma unroll
        for (int cb = 0; cb < 128; cb += 32) {
            uint32_t gr[32], ur[32];
            LDTM_X32(gr, tmem + cb);
            LDTM_X32(ur, tmem + 128 + cb);
            TC_WAIT_LD();
            if (ok) {
                uint32_t hw[16];
#pragma unroll
                for (int j = 0; j < 16; j++) {
                    float g0 = __uint_as_float(gr[2*j]);
                    float g1 = __uint_as_float(gr[2*j+1]);
                    float h0 = g0 / (1.f + __expf(-g0)) * __uint_as_float(ur[2*j]);
                    float h1 = g1 / (1.f + __expf(-g1)) * __uint_as_float(ur[2*j+1]);
                    hw[j] = packh2(h0, h1);
                }
#pragma unroll
                for (int j = 0; j < 16; j += 4)
                    *(uint4*)(hrow + cb/2 + j) =
                        make_uint4(hw[j], hw[j+1], hw[j+2], hw[j+3]);
            }
        }
    }
    __syncthreads();
    if (wid == 0) TC_DEALLOC(tmem, 256);

#else
    // ============ fp16 mma.sync fallback, double-buffered ==============
    extern __shared__ uint32_t smw[];
    const int rg = (wid >> 2) * 32;     // warp row group
    const int cg = (wid & 3) * 32;      // warp col group

    // A fill tasks (2): row = t>>3, kq = t&7 (4 fp32 -> 2 half2 words)
    const float* aptr[2]; int a_row[2], a_kq[2];
#pragma unroll
    for (int i = 0; i < 2; i++) {
        int t = tid + i * 512;
        a_row[i] = t >> 3; a_kq[i] = t & 7;
        int gr = m0 + a_row[i];
        aptr[i] = (gr < cnt) ? (x + (size_t)d_tok[off + gr] * HIDDEN + a_kq[i] * 4) : nullptr;
    }
    // W fill task (1 per matrix): kp = tid>>5 (k pair), n4 = tid&31
    const int kp = tid >> 5, n4 = tid & 31;
    const float* w1f = w1b + (size_t)(kp * 2) * INTER + n4 * 4;
    const float* w3f = w3b + (size_t)(kp * 2) * INTER + n4 * 4;

    uint32_t apf[4], w1pf[4], w3pf[4];
    auto loadregs = [&](int k0) {
#pragma unroll
        for (int i = 0; i < 2; i++) {
            float4 v = make_float4(0.f, 0.f, 0.f, 0.f);
            if (aptr[i]) v = *(const float4*)(aptr[i] + k0);
            apf[2*i]   = packh2(v.x, v.y);
            apf[2*i+1] = packh2(v.z, v.w);
        }
        float4 u0 = *(const float4*)(w1f + (size_t)k0 * INTER);
        float4 u1 = *(const float4*)(w1f + (size_t)(k0 + 1) * INTER);
        w1pf[0] = packh2(u0.x, u1.x); w1pf[1] = packh2(u0.y, u1.y);
        w1pf[2] = packh2(u0.z, u1.z); w1pf[3] = packh2(u0.w, u1.w);
        float4 q0 = *(const float4*)(w3f + (size_t)k0 * INTER);
        float4 q1 = *(const float4*)(w3f + (size_t)(k0 + 1) * INTER);
        w3pf[0] = packh2(q0.x, q1.x); w3pf[1] = packh2(q0.y, q1.y);
        w3pf[2] = packh2(q0.z, q1.z); w3pf[3] = packh2(q0.w, q1.w);
    };
    auto sts = [&](int buf) {
        uint32_t* As  = smw + buf * G1_FB_WORDS;
        uint32_t* W1s = As + 128 * SSTR;
        uint32_t* W3s = W1s + 128 * SSTR;
#pragma unroll
        for (int i = 0; i < 2; i++) {
            As[a_row[i] * SSTR + a_kq[i] * 2]     = apf[2*i];
            As[a_row[i] * SSTR + a_kq[i] * 2 + 1] = apf[2*i+1];
        }
#pragma unroll
        for (int j = 0; j < 4; j++) {
            W1s[(n4 * 4 + j) * SSTR + kp] = w1pf[j];
            W3s[(n4 * 4 + j) * SSTR + kp] = w3pf[j];
        }
    };

    float gacc[2][4][4], uacc[2][4][4];
#pragma unroll
    for (int mi = 0; mi < 2; mi++)
#pragma unroll
        for (int ni = 0; ni < 4; ni++)
#pragma unroll
            for (int r = 0; r < 4; r++) { gacc[mi][ni][r] = 0.f; uacc[mi][ni][r] = 0.f; }

    loadregs(0); sts(0);
    __syncthreads();

    const int NC = HIDDEN / FBK;   // 64
    for (int c = 0; c < NC; c++) {
        if (c + 1 < NC) loadregs((c + 1) * FBK);
        const int buf = c & 1;
        uint32_t* As  = smw + buf * G1_FB_WORDS;
        uint32_t* W1s = As + 128 * SSTR;
        uint32_t* W3s = W1s + 128 * SSTR;
#pragma unroll
        for (int kk = 0; kk < 2; kk++) {
            const int ko = kk * 8;
            uint32_t a[2][4];
#pragma unroll
            for (int mi = 0; mi < 2; mi++) {
                int rb = rg + mi * 16;
                a[mi][0] = As[(rb + g)     * SSTR + ko + tg];
                a[mi][1] = As[(rb + g + 8) * SSTR + ko + tg];
                a[mi][2] = As[(rb + g)     * SSTR + ko + tg + 4];
                a[mi][3] = As[(rb + g + 8) * SSTR + ko + tg + 4];
            }
#pragma unroll
            for (int ni = 0; ni < 4; ni++) {
                int cb = cg + ni * 8;
                uint32_t b0 = W1s[(cb + g) * SSTR + ko + tg];
                uint32_t b1 = W1s[(cb + g) * SSTR + ko + tg + 4];
                uint32_t c0 = W3s[(cb + g) * SSTR + ko + tg];
                uint32_t c1 = W3s[(cb + g) * SSTR + ko + tg + 4];
                mma16816(gacc[0][ni], a[0], b0, b1);
                mma16816(gacc[1][ni], a[1], b0, b1);
                mma16816(uacc[0][ni], a[0], c0, c1);
                mma16816(uacc[1][ni], a[1], c0, c1);
            }
        }
        if (c + 1 < NC) sts(buf ^ 1);
        __syncthreads();
    }

#pragma unroll
    for (int mi = 0; mi < 2; mi++) {
#pragma unroll
        for (int ni = 0; ni < 4; ni++) {
            int lr0 = rg + mi * 16 + g;
            int lr1 = lr0 + 8;
            int col = n0 + cg + ni * 8 + tg * 2;
            if (m0 + lr0 < cnt) {
                float g0 = gacc[mi][ni][0], g1 = gacc[mi][ni][1];
                float h0 = g0 / (1.f + __expf(-g0)) * uacc[mi][ni][0];
                float h1 = g1 / (1.f + __expf(-g1)) * uacc[mi][ni][1];
                d_hbuf[((size_t)(off + m0 + lr0) * INTER + col) >> 1] = packh2(h0, h1);
            }
            if (m0 + lr1 < cnt) {
                float g2 = gacc[mi][ni][2], g3 = gacc[mi][ni][3];
                float h2 = g2 / (1.f + __expf(-g2)) * uacc[mi][ni][2];
                float h3 = g3 / (1.f + __expf(-g3)) * uacc[mi][ni][3];
                d_hbuf[((size_t)(off + m0 + lr1) * INTER + col) >> 1] = packh2(h2, h3);
            }
        }
    }
#endif
}

// ---------------------------------------------------------------------------
// GEMM2: y = h @ W2 -> d_ybuf  (h is packed fp16)
// ---------------------------------------------------------------------------
__global__ __launch_bounds__(512, 1)
void gemm2_kernel(const float* __restrict__ w2g) {
    const int e    = blockIdx.x >> 5;
    const int cnt  = d_cnt[e];
    const int m0   = (blockIdx.x & 31) * BM;
    if (m0 >= cnt) return;
    const int n0   = blockIdx.y * BN;
    const int off  = d_off[e];
    const int tid = threadIdx.x, wid = tid >> 5, lid = tid & 31;
    const int g = lid >> 2, tg = lid & 3;

    const float* w2b = w2g + (size_t)e * INTER * HIDDEN + n0;

#if HAS_TCGEN05
    extern __shared__ char smem[];
    const uint32_t sb = smem_u32(smem);

    if (wid == 0) TC_ALLOC(sb + SMEM_TMEM, 128);
    if (tid == 0)
        for (int s = 0; s < NSTG; s++) MBAR_INIT(sb + SMEM_MBAR + 8 * s, 1);
    __syncthreads();
    uint32_t tmem;
    asm volatile("ld.shared.b32 %0, [%1];" : "=r"(tmem) : "r"(sb + SMEM_TMEM));
    if (wid == 0) TC_RELINQ();

    // A tasks (2): m = t>>3, kb = t&7; read 16B of packed fp16 directly
    const uint32_t* hr[2]; uint32_t a_sw[2];
#pragma unroll
    for (int i = 0; i < 2; i++) {
        int t = tid + i * 512, m = t >> 3, kb = t & 7;
        hr[i]   = d_hbuf + (size_t)(off + m0 + m) * (INTER / 2) + kb * 4;
        a_sw[i] = swz128((uint32_t)(m * 128 + kb * 16));
    }
    const float* w2t[2]; uint32_t w_sw[2];
#pragma unroll
    for (int i = 0; i < 2; i++) {
        int t = tid + i * 512, n = t & 127, kb = t >> 7;
        w2t[i] = w2b + (size_t)(kb * 8) * HIDDEN + n;
        w_sw[i] = swz128((uint32_t)(n * 128 + kb * 16));
    }

    uint32_t apf[8], wpf[8];
    auto prefetch = [&](int c) {
#pragma unroll
        for (int i = 0; i < 2; i++) {
            uint4 v = *(const uint4*)(hr[i] + c * 32);
            apf[4*i] = v.x; apf[4*i+1] = v.y; apf[4*i+2] = v.z; apf[4*i+3] = v.w;
        }
        const int k0 = c * BK_TC;
#pragma unroll
        for (int i = 0; i < 2; i++) {
            float t2[8];
#pragma unroll
            for (int j = 0; j < 8; j++)
                t2[j] = w2t[i][(size_t)(k0 + j) * HIDDEN];
#pragma unroll
            for (int j = 0; j < 4; j++)
                wpf[4*i+j] = packh2(t2[2*j], t2[2*j+1]);
        }
    };

    prefetch(0);
    const int NC = INTER / BK_TC;   // 88
    for (int c = 0; c < NC; c++) {
        const int s = c & (NSTG - 1);
        if (c >= NSTG) MBAR_WAIT(sb + SMEM_MBAR + 8 * s, ((c >> 2) - 1) & 1);

        const uint32_t stg = sb + SMEM_DATA + s * G2_STAGE;
#pragma unroll
        for (int i = 0; i < 2; i++) {
            STS128(stg + a_sw[i], apf[4*i], apf[4*i+1], apf[4*i+2], apf[4*i+3]);
            STS128(stg + TILE_BYTES + w_sw[i], wpf[4*i], wpf[4*i+1], wpf[4*i+2], wpf[4*i+3]);
        }
        __syncthreads();

        if (tid == 0) {
            FENCE_ASYNC();
            uint64_t ad = make_desc(stg);
            uint64_t bd = make_desc(stg + TILE_BYTES);
#pragma unroll
            for (int ks = 0; ks < 4; ks++)
                mma_f16_ss(tmem, ad + ks * 2, bd + ks * 2, (c > 0 || ks > 0) ? 1u : 0u);
            TC_COMMIT(sb + SMEM_MBAR + 8 * s);
        }
        if (c + 1 < NC) prefetch(c + 1);
    }

    MBAR_WAIT(sb + SMEM_MBAR + 8 * ((NC - 1) & 3), ((NC - 1) >> 2) & 1);
    TC_FENCE_AFTER();
    if (wid < 4) {
        const int mr = wid * 32 + lid;
        const bool ok = (m0 + mr) < cnt;
        float* yrow = d_ybuf + (size_t)(off + m0 + mr) * HIDDEN + n0;
#pragma unroll
        for (int cb = 0; cb < 128; cb += 32) {
            uint32_t yr[32];
            LDTM_X32(yr, tmem + cb);
            TC_WAIT_LD();
            if (ok) {
#pragma unroll
                for (int j = 0; j < 32; j += 4) {
                    float4 v;
                    v.x = __uint_as_float(yr[j]);     v.y = __uint_as_float(yr[j+1]);
                    v.z = __uint_as_float(yr[j+2]);   v.w = __uint_as_float(yr[j+3]);
                    *(float4*)(yrow + cb + j) = v;
                }
            }
        }
    }
    __syncthreads();
    if (wid == 0) TC_DEALLOC(tmem, 128);

#else
    // ============ fp16 mma.sync fallback, double-buffered ==============
    extern __shared__ uint32_t smw[];
    const int rg = (wid >> 2) * 32;
    const int cg = (wid & 3) * 32;

    const uint32_t* hptr[2]; int a_row[2], a_kq[2];
#pragma unroll
    for (int i = 0; i < 2; i++) {
        int t = tid + i * 512;
        a_row[i] = t >> 3; a_kq[i] = t & 7;
        hptr[i] = d_hbuf + (size_t)(off + m0 + a_row[i]) * (INTER / 2) + a_kq[i] * 2;
    }
    const int kp = tid >> 5, n4 = tid & 31;
    const float* w2f = w2b + (size_t)(kp * 2) * HIDDEN + n4 * 4;

    uint32_t apf[4], wpf[4];
    auto loadregs = [&](int c) {
#pragma unroll
        for (int i = 0; i < 2; i++) {
            uint2 v = *(const uint2*)(hptr[i] + c * 16);
            apf[2*i] = v.x; apf[2*i+1] = v.y;
        }
        const int k0 = c * FBK;
        float4 u0 = *(const float4*)(w2f + (size_t)k0 * HIDDEN);
        float4 u1 = *(const float4*)(w2f + (size_t)(k0 + 1) * HIDDEN);
        wpf[0] = packh2(u0.x, u1.x); wpf[1] = packh2(u0.y, u1.y);
        wpf[2] = packh2(u0.z, u1.z); wpf[3] = packh2(u0.w, u1.w);
    };
    auto sts = [&](int buf) {
        uint32_t* As = smw + buf * G2_FB_WORDS;
        uint32_t* Ws = As + 128 * SSTR;
#pragma unroll
        for (int i = 0; i < 2; i++) {
            As[a_row[i] * SSTR + a_kq[i] * 2]     = apf[2*i];
            As[a_row[i] * SSTR + a_kq[i] * 2 + 1] = apf[2*i+1];
        }
#pragma unroll
        for (int j = 0; j < 4; j++)
            Ws[(n4 * 4 + j) * SSTR + kp] = wpf[j];
    };

    float acc[2][4][4];
#pragma unroll
    for (int mi = 0; mi < 2; mi++)
#pragma unroll
        for (int ni = 0; ni < 4; ni++)
#pragma unroll
            for (int r = 0; r < 4; r++) acc[mi][ni][r] = 0.f;

    loadregs(0); sts(0);
    __syncthreads();

    const int NC = INTER / FBK;   // 176
    for (int c = 0; c < NC; c++) {
        if (c + 1 < NC) loadregs(c + 1);
        const int buf = c & 1;
        uint32_t* As = smw + buf * G2_FB_WORDS;
        uint32_t* Ws = As + 128 * SSTR;
#pragma unroll
        for (int kk = 0; kk < 2; kk++) {
            const int ko = kk * 8;
            uint32_t a[2][4];
#pragma unroll
            for (int mi = 0; mi < 2; mi++) {
                int rb = rg + mi * 16;
                a[mi][0] = As[(rb + g)     * SSTR + ko + tg];
                a[mi][1] = As[(rb + g + 8) * SSTR + ko + tg];
                a[mi][2] = As[(rb + g)     * SSTR + ko + tg + 4];
                a[mi][3] = As[(rb + g + 8) * SSTR + ko + tg + 4];
            }
#pragma unroll
            for (int ni = 0; ni < 4; ni++) {
                int cb = cg + ni * 8;
                uint32_t b0 = Ws[(cb + g) * SSTR + ko + tg];
                uint32_t b1 = Ws[(cb + g) * SSTR + ko + tg + 4];
                mma16816(acc[0][ni], a[0], b0, b1);
                mma16816(acc[1][ni], a[1], b0, b1);
            }
        }
        if (c + 1 < NC) sts(buf ^ 1);
        __syncthreads();
    }

#pragma unroll
    for (int mi = 0; mi < 2; mi++) {
#pragma unroll
        for (int ni = 0; ni < 4; ni++) {
            int lr0 = rg + mi * 16 + g;
            int lr1 = lr0 + 8;
            int col = n0 + cg + ni * 8 + tg * 2;
            if (m0 + lr0 < cnt)
                *(float2*)(d_ybuf + (size_t)(off + m0 + lr0) * HIDDEN + col) =
                    make_float2(acc[mi][ni][0], acc[mi][ni][1]);
            if (m0 + lr1 < cnt)
                *(float2*)(d_ybuf + (size_t)(off + m0 + lr1) * HIDDEN + col) =
                    make_float2(acc[mi][ni][2], acc[mi][ni][3]);
        }
    }
#endif
}

// ---------------------------------------------------------------------------
// Combine: out[t] = ew[2t]*y[pos[2t]] + ew[2t+1]*y[pos[2t+1]]
// ---------------------------------------------------------------------------
__global__ __launch_bounds__(256)
void combine_kernel(const float* __restrict__ ew, float* __restrict__ out) {
    const int t = blockIdx.x;
    const int p0 = d_pos[2 * t], p1 = d_pos[2 * t + 1];
    const float w0 = ew[2 * t], w1 = ew[2 * t + 1];
    const float4* y0 = (const float4*)(d_ybuf + (size_t)p0 * HIDDEN);
    const float4* y1 = (const float4*)(d_ybuf + (size_t)p1 * HIDDEN);
    float4* o = (float4*)(out + (size_t)t * HIDDEN);
#pragma unroll
    for (int i = threadIdx.x; i < HIDDEN / 4; i += 256) {
        float4 a = y0[i], b = y1[i], r;
        r.x = w0 * a.x + w1 * b.x; r.y = w0 * a.y + w1 * b.y;
        r.z = w0 * a.z + w1 * b.z; r.w = w0 * a.w + w1 * b.w;
        o[i] = r;
    }
}

// ---------------------------------------------------------------------------
// launch — inputs: x, expert_weights, w1, w2, w3, expert_indices
// ---------------------------------------------------------------------------
extern "C" void kernel_launch(void* const* d_in, const int* in_sizes, int n_in,
                              void* d_out, int out_size) {
    const float* x  = (const float*)d_in[0];
    const float* ew = (const float*)d_in[1];
    const float* w1 = (const float*)d_in[2];
    const float* w2 = (const float*)d_in[3];
    const float* w3 = (const float*)d_in[4];
    const int*   ei = (const int*)d_in[5];
    float* out = (float*)d_out;

    static int attr_done = 0;
    if (!attr_done) {
        cudaFuncSetAttribute(gemm1_kernel, cudaFuncAttributeMaxDynamicSharedMemorySize, G1_SMEM);
        cudaFuncSetAttribute(gemm2_kernel, cudaFuncAttributeMaxDynamicSharedMemorySize, G2_SMEM);
        attr_done = 1;
    }

    route_kernel<<<1, 256>>>(ei);

    dim3 g1(NEXP * MAXMT, INTER / BN);   // 256 x 44
    gemm1_kernel<<<g1, 512, G1_SMEM>>>(x, w1, w3);

    dim3 g2(NEXP * MAXMT, HIDDEN / BN);  // 256 x 16
    gemm2_kernel<<<g2, 512, G2_SMEM>>>(w2);

    combine_kernel<<<TOKENS, 256>>>(ew, out);
}